// round 3
// baseline (speedup 1.0000x reference)
#include <cuda_runtime.h>
#include <cuda_bf16.h>
#include <math.h>

#define NN     200000
#define EE     3200000
#define GG     256
#define HID    128
#define NLAYER 3
#define EPSV   1e-5f

#define NCHUNK 1024
#define CHUNK  196              // ceil(NN/NCHUNK)
#define BM     64               // rows per block
#define APITCH 132              // padded A-tile pitch (floats)
#define FUSED_SMEM ((BM*APITCH + HID*HID) * 4)

// ---------------- scratch (device globals; no allocation allowed) ----------------
__device__ float g_bufA[(size_t)NN * HID];
__device__ float g_bufB[(size_t)NN * HID];
__device__ int   g_rowptr[NN + 1];
__device__ int   g_cursor[NN];
__device__ int   g_cols[EE];
__device__ float g_vals[EE];
__device__ int   g_chunk[NCHUNK];
__device__ float g_sum[GG * HID];
__device__ float g_sumsq[GG * HID];
__device__ float g_scale[GG * HID];
__device__ float g_shift[GG * HID];
__device__ int   g_cnt[GG];

// ---------------- node embedding + input projection ----------------
__global__ void embed_kernel(const float* __restrict__ x,
                             const float* __restrict__ Win,
                             const float* __restrict__ bin,
                             float* __restrict__ out) {
    __shared__ float Ws[15 * HID];
    __shared__ float bs[HID];
    int tid = threadIdx.x; // blockDim = 128
    for (int i = tid; i < 15 * HID; i += 128) Ws[i] = Win[i];
    bs[tid] = bin[tid];
    __syncthreads();
    const float dts[4] = {1.0f, 0.1f, 0.01f, 0.001f};
    for (int n = blockIdx.x; n < NN; n += gridDim.x) {
        float t  = x[n * 3 + 0];
        float ar = x[n * 3 + 1];
        float ap = x[n * 3 + 2];
        int ti = min(max(__float2int_rz(t), 0), 5);
        float la = log1pf(ar);
        float acc = bs[tid] + Ws[ti * HID + tid] + la * Ws[6 * HID + tid];
        #pragma unroll
        for (int k = 0; k < 4; k++) {
            float sv, cv;
            sincosf(ap * dts[k], &sv, &cv);
            acc += sv * Ws[(7 + 2 * k) * HID + tid] + cv * Ws[(8 + 2 * k) * HID + tid];
        }
        out[(size_t)n * HID + tid] = acc;
    }
}

// ---------------- per-graph node counts ----------------
__global__ void hist_batch(const int* __restrict__ batch) {
    __shared__ int h[GG];
    for (int i = threadIdx.x; i < GG; i += blockDim.x) h[i] = 0;
    __syncthreads();
    for (int i = blockIdx.x * blockDim.x + threadIdx.x; i < NN; i += gridDim.x * blockDim.x)
        atomicAdd(&h[batch[i]], 1);
    __syncthreads();
    for (int i = threadIdx.x; i < GG; i += blockDim.x)
        if (h[i]) atomicAdd(&g_cnt[i], h[i]);
}

// ---------------- CSR build: histogram -> scan -> scatter ----------------
__global__ void hist_rows(const int* __restrict__ er) {
    int i = blockIdx.x * blockDim.x + threadIdx.x;
    if (i < EE) atomicAdd(&g_cursor[er[i]], 1);
}

__global__ void scan_chunks() {
    int t = blockIdx.x * blockDim.x + threadIdx.x;
    if (t >= NCHUNK) return;
    int base = t * CHUNK;
    int lim = min(base + CHUNK, NN);
    int s = 0;
    for (int i = base; i < lim; i++) s += g_cursor[i];
    g_chunk[t] = s;
}

__global__ void scan_excl() {
    __shared__ int s[NCHUNK];
    int t = threadIdx.x;
    int v = g_chunk[t];
    s[t] = v;
    __syncthreads();
    for (int off = 1; off < NCHUNK; off <<= 1) {
        int add = (t >= off) ? s[t - off] : 0;
        __syncthreads();
        s[t] += add;
        __syncthreads();
    }
    g_chunk[t] = s[t] - v;
}

__global__ void scan_write() {
    int t = blockIdx.x * blockDim.x + threadIdx.x;
    if (t >= NCHUNK) return;
    if (t == 0) g_rowptr[NN] = EE;
    int base = t * CHUNK;
    int lim = min(base + CHUNK, NN);
    int run = g_chunk[t];
    for (int i = base; i < lim; i++) {
        int c = g_cursor[i];
        g_rowptr[i] = run;
        g_cursor[i] = run;
        run += c;
    }
}

__global__ void scatter_edges(const int* __restrict__ er,
                              const int* __restrict__ ec,
                              const float* __restrict__ ev) {
    int i = blockIdx.x * blockDim.x + threadIdx.x;
    if (i < EE) {
        int p = atomicAdd(&g_cursor[er[i]], 1);
        g_cols[p] = ec[i];
        g_vals[p] = ev[i];
    }
}

// ---------------- FUSED: SpMM-gather -> GEMM -> stats ----------------
// Block owns 64 rows. Phase 1: 8 warps gather/aggregate 8 rows each (edges via
// shfl-broadcast, 2x unrolled for MLP) into smem A-tile. Phase 2: register-blocked
// 64x128 @ 128x128 GEMM. Epilogue: y=acc+b to global + per-graph sum/sumsq stats.
__global__ __launch_bounds__(256, 2)
void fused_layer(const float* __restrict__ H, const float* __restrict__ W,
                 const float* __restrict__ bias, const int* __restrict__ batch,
                 float* __restrict__ Y) {
    extern __shared__ float sm[];
    float* Asm = sm;                 // [BM][APITCH]
    float* Wsm = sm + BM * APITCH;   // [HID][HID]
    int tid = threadIdx.x;
    int row0 = blockIdx.x * BM;
    int wid = tid >> 5, lane = tid & 31;

    // load W tile (issue early; overlaps with gather below)
    const float4* Wg = (const float4*)W;
    float4* Wd = (float4*)Wsm;
    #pragma unroll
    for (int i = 0; i < 16; i++) Wd[tid + i * 256] = Wg[tid + i * 256];

    // Phase 1: gather-aggregate. warp w handles rows [w*8, w*8+8)
    int c4 = lane * 4;
    for (int i = 0; i < 8; i++) {
        int r = wid * 8 + i;
        int row = row0 + r;
        int beg = __ldg(&g_rowptr[row]);
        int end = __ldg(&g_rowptr[row + 1]);
        float4 acc = make_float4(0.f, 0.f, 0.f, 0.f);
        for (int base = beg; base < end; base += 32) {
            int cnt = min(32, end - base);
            int c = 0; float v = 0.f;
            if (lane < cnt) { c = __ldg(&g_cols[base + lane]); v = __ldg(&g_vals[base + lane]); }
            int j = 0;
            for (; j + 1 < cnt; j += 2) {
                int   c0 = __shfl_sync(0xFFFFFFFFu, c, j);
                float v0 = __shfl_sync(0xFFFFFFFFu, v, j);
                int   c1 = __shfl_sync(0xFFFFFFFFu, c, j + 1);
                float v1 = __shfl_sync(0xFFFFFFFFu, v, j + 1);
                float4 h0 = *(const float4*)&H[(size_t)c0 * HID + c4];
                float4 h1 = *(const float4*)&H[(size_t)c1 * HID + c4];
                acc.x = fmaf(v0, h0.x, acc.x); acc.y = fmaf(v0, h0.y, acc.y);
                acc.z = fmaf(v0, h0.z, acc.z); acc.w = fmaf(v0, h0.w, acc.w);
                acc.x = fmaf(v1, h1.x, acc.x); acc.y = fmaf(v1, h1.y, acc.y);
                acc.z = fmaf(v1, h1.z, acc.z); acc.w = fmaf(v1, h1.w, acc.w);
            }
            if (j < cnt) {
                int   c0 = __shfl_sync(0xFFFFFFFFu, c, j);
                float v0 = __shfl_sync(0xFFFFFFFFu, v, j);
                float4 h0 = *(const float4*)&H[(size_t)c0 * HID + c4];
                acc.x = fmaf(v0, h0.x, acc.x); acc.y = fmaf(v0, h0.y, acc.y);
                acc.z = fmaf(v0, h0.z, acc.z); acc.w = fmaf(v0, h0.w, acc.w);
            }
        }
        *(float4*)&Asm[r * APITCH + c4] = acc;
    }
    __syncthreads();

    // Phase 2: GEMM 64x128 @ 128x128
    int tx = tid & 15, ty = tid >> 4;
    int cb = tx * 8, rb = ty * 4;
    float acc[4][8];
    #pragma unroll
    for (int r = 0; r < 4; r++)
        #pragma unroll
        for (int j = 0; j < 8; j++) acc[r][j] = 0.f;

    #pragma unroll 4
    for (int k = 0; k < HID; k++) {
        float a[4];
        #pragma unroll
        for (int r = 0; r < 4; r++) a[r] = Asm[(rb + r) * APITCH + k];
        float4 w0 = *(float4*)&Wsm[k * HID + cb];
        float4 w1 = *(float4*)&Wsm[k * HID + cb + 4];
        float wv[8] = {w0.x, w0.y, w0.z, w0.w, w1.x, w1.y, w1.z, w1.w};
        #pragma unroll
        for (int r = 0; r < 4; r++)
            #pragma unroll
            for (int j = 0; j < 8; j++)
                acc[r][j] = fmaf(a[r], wv[j], acc[r][j]);
    }

    float bv[8];
    #pragma unroll
    for (int j = 0; j < 8; j++) bv[j] = bias[cb + j];

    float s[8], q[8];
    #pragma unroll
    for (int j = 0; j < 8; j++) { s[j] = 0.f; q[j] = 0.f; }

    #pragma unroll
    for (int r = 0; r < 4; r++) {
        float y[8];
        #pragma unroll
        for (int j = 0; j < 8; j++) {
            y[j] = acc[r][j] + bv[j];
            s[j] += y[j];
            q[j] += y[j] * y[j];
        }
        size_t off = (size_t)(row0 + rb + r) * HID + cb;
        *(float4*)&Y[off]     = make_float4(y[0], y[1], y[2], y[3]);
        *(float4*)&Y[off + 4] = make_float4(y[4], y[5], y[6], y[7]);
    }

    int gfirst = batch[row0];
    int glast  = batch[row0 + BM - 1];
    if (gfirst == glast) {
        float* red = Asm; // reuse
        __syncthreads();
        *(float4*)&red[ty * APITCH + cb]     = make_float4(s[0], s[1], s[2], s[3]);
        *(float4*)&red[ty * APITCH + cb + 4] = make_float4(s[4], s[5], s[6], s[7]);
        __syncthreads();
        #pragma unroll
        for (int st = 8; st >= 1; st >>= 1) {
            if (ty < st) {
                #pragma unroll
                for (int j = 0; j < 8; j++)
                    red[ty * APITCH + cb + j] += red[(ty + st) * APITCH + cb + j];
            }
            __syncthreads();
        }
        if (ty == 0) {
            #pragma unroll
            for (int j = 0; j < 8; j++)
                atomicAdd(&g_sum[gfirst * HID + cb + j], red[cb + j]);
        }
        __syncthreads();
        *(float4*)&red[ty * APITCH + cb]     = make_float4(q[0], q[1], q[2], q[3]);
        *(float4*)&red[ty * APITCH + cb + 4] = make_float4(q[4], q[5], q[6], q[7]);
        __syncthreads();
        #pragma unroll
        for (int st = 8; st >= 1; st >>= 1) {
            if (ty < st) {
                #pragma unroll
                for (int j = 0; j < 8; j++)
                    red[ty * APITCH + cb + j] += red[(ty + st) * APITCH + cb + j];
            }
            __syncthreads();
        }
        if (ty == 0) {
            #pragma unroll
            for (int j = 0; j < 8; j++)
                atomicAdd(&g_sumsq[gfirst * HID + cb + j], red[cb + j]);
        }
    } else {
        #pragma unroll
        for (int r = 0; r < 4; r++) {
            int g = batch[row0 + rb + r];
            #pragma unroll
            for (int j = 0; j < 8; j++) {
                float y = acc[r][j] + bv[j];
                atomicAdd(&g_sum[g * HID + cb + j], y);
                atomicAdd(&g_sumsq[g * HID + cb + j], y * y);
            }
        }
    }
}

// ---------------- GraphNorm stat finalize ----------------
__global__ void finalize_stats(const float* __restrict__ alphas,
                               const float* __restrict__ gammas,
                               const float* __restrict__ betas, int l) {
    int i = blockIdx.x * blockDim.x + threadIdx.x;
    if (i >= GG * HID) return;
    int g = i >> 7, c = i & 127;
    float cnt = fmaxf((float)g_cnt[g], 1.f);
    float m  = g_sum[i] / cnt;
    float e2 = g_sumsq[i] / cnt;
    float al = alphas[l];
    float var = e2 - al * (2.f - al) * m * m;
    float rstd = rsqrtf(fmaxf(var, 0.f) + EPSV);
    float ga = gammas[l * HID + c];
    g_scale[i] = rstd * ga;
    g_shift[i] = betas[l * HID + c] - al * m * rstd * ga;
}

// ---------------- normalize (+ optional relu), may be in-place ----------------
__global__ void norm_kernel(const float* __restrict__ Y, const int* __restrict__ batch,
                            float* __restrict__ out, int relu) {
    int idx = blockIdx.x * blockDim.x + threadIdx.x;
    if (idx >= NN * 32) return;
    int n = idx >> 5, c4 = (idx & 31) * 4;
    int g = batch[n];
    float4 y  = *(const float4*)&Y[(size_t)n * HID + c4];
    float4 sc = *(const float4*)&g_scale[g * HID + c4];
    float4 sh = *(const float4*)&g_shift[g * HID + c4];
    float4 r;
    r.x = fmaf(y.x, sc.x, sh.x);
    r.y = fmaf(y.y, sc.y, sh.y);
    r.z = fmaf(y.z, sc.z, sh.z);
    r.w = fmaf(y.w, sc.w, sh.w);
    if (relu) {
        r.x = fmaxf(r.x, 0.f); r.y = fmaxf(r.y, 0.f);
        r.z = fmaxf(r.z, 0.f); r.w = fmaxf(r.w, 0.f);
    }
    *(float4*)&out[(size_t)n * HID + c4] = r;
}

// ---------------- launch ----------------
extern "C" void kernel_launch(void* const* d_in, const int* in_sizes, int n_in,
                              void* d_out, int out_size) {
    const float* x      = (const float*)d_in[0];
    const int*   er     = (const int*)d_in[1];
    const int*   ec     = (const int*)d_in[2];
    const float* ev     = (const float*)d_in[3];
    const int*   batch  = (const int*)d_in[4];
    const float* Win    = (const float*)d_in[5];
    const float* bin    = (const float*)d_in[6];
    const float* Ws     = (const float*)d_in[7];
    const float* bs     = (const float*)d_in[8];
    const float* alphas = (const float*)d_in[9];
    const float* gammas = (const float*)d_in[10];
    const float* betas  = (const float*)d_in[11];
    float* out = (float*)d_out;

    cudaFuncSetAttribute(fused_layer, cudaFuncAttributeMaxDynamicSharedMemorySize, FUSED_SMEM);

    float *A, *B;
    void *pcnt, *pcur, *psum, *psq;
    cudaGetSymbolAddress((void**)&A, g_bufA);
    cudaGetSymbolAddress((void**)&B, g_bufB);
    cudaGetSymbolAddress(&pcnt, g_cnt);
    cudaGetSymbolAddress(&pcur, g_cursor);
    cudaGetSymbolAddress(&psum, g_sum);
    cudaGetSymbolAddress(&psq,  g_sumsq);

    cudaMemsetAsync(pcnt, 0, GG * sizeof(int), 0);
    cudaMemsetAsync(pcur, 0, NN * sizeof(int), 0);

    embed_kernel<<<2048, 128>>>(x, Win, bin, A);
    hist_batch<<<256, 256>>>(batch);

    hist_rows<<<EE / 256, 256>>>(er);
    scan_chunks<<<4, 256>>>();
    scan_excl<<<1, NCHUNK>>>();
    scan_write<<<4, 256>>>();
    scatter_edges<<<EE / 256, 256>>>(er, ec, ev);

    // ping-pong: h lives in A for even layers, B for odd layers. fused writes y to
    // the other buffer; norm is applied in place (last layer -> d_out).
    for (int l = 0; l < NLAYER; l++) {
        const float* h = (l & 1) ? B : A;
        float* y = (l & 1) ? A : B;

        cudaMemsetAsync(psum, 0, GG * HID * sizeof(float), 0);
        cudaMemsetAsync(psq,  0, GG * HID * sizeof(float), 0);
        fused_layer<<<NN / BM, 256, FUSED_SMEM>>>(h, Ws + (size_t)l * HID * HID,
                                                  bs + l * HID, batch, y);
        finalize_stats<<<(GG * HID) / 256, 256>>>(alphas, gammas, betas, l);
        float* nout = (l == NLAYER - 1) ? out : y; // in place except final
        norm_kernel<<<(NN * 32) / 256, 256>>>(y, batch, nout, (l < NLAYER - 1) ? 1 : 0);
    }
}

// round 6
// speedup vs baseline: 1.1973x; 1.1973x over previous
#include <cuda_runtime.h>
#include <cuda_bf16.h>
#include <math.h>

#define NN     200000
#define EE     3200000
#define GG     256
#define HID    128
#define NLAYER 3
#define EPSV   1e-5f

#define SCANT  1024
#define CHUNK  196              // ceil(NN/SCANT)
#define BM     64               // gemm rows per block
#define APITCH 132              // padded A-tile pitch (floats)
#define GEMM_SMEM ((BM*APITCH + HID*HID) * 4)

// ---------------- scratch (device globals; no allocation allowed) ----------------
__device__ float g_bufA[(size_t)NN * HID];
__device__ float g_bufB[(size_t)NN * HID];
__device__ int   g_rowptr[NN + 1];
__device__ int   g_cursor[NN];
__device__ int   g_cols[EE];
__device__ float g_vals[EE];
__device__ float g_sum[GG * HID];
__device__ float g_sumsq[GG * HID];
__device__ float g_scale[GG * HID];
__device__ float g_shift[GG * HID];
__device__ int   g_cnt[GG];

// ---------------- node embedding + input projection (also zeroes all scratch) ----------------
__global__ void embed_kernel(const float* __restrict__ x,
                             const float* __restrict__ Win,
                             const float* __restrict__ bin,
                             float* __restrict__ out) {
    __shared__ float Ws[15 * HID];
    __shared__ float bs[HID];
    int tid = threadIdx.x; // blockDim = 128
    // fold in zeroing of scratch used by later kernels (saves memset launches)
    int gtid = blockIdx.x * 128 + tid; // 262144 threads total
    if (gtid < NN) g_cursor[gtid] = 0;
    if (gtid < GG) g_cnt[gtid] = 0;
    if (gtid < GG * HID) { g_sum[gtid] = 0.f; g_sumsq[gtid] = 0.f; }

    for (int i = tid; i < 15 * HID; i += 128) Ws[i] = Win[i];
    bs[tid] = bin[tid];
    __syncthreads();
    const float dts[4] = {1.0f, 0.1f, 0.01f, 0.001f};
    for (int n = blockIdx.x; n < NN; n += gridDim.x) {
        float t  = x[n * 3 + 0];
        float ar = x[n * 3 + 1];
        float ap = x[n * 3 + 2];
        int ti = min(max(__float2int_rz(t), 0), 5);
        float la = log1pf(ar);
        float acc = bs[tid] + Ws[ti * HID + tid] + la * Ws[6 * HID + tid];
        #pragma unroll
        for (int k = 0; k < 4; k++) {
            float sv, cv;
            sincosf(ap * dts[k], &sv, &cv);
            acc += sv * Ws[(7 + 2 * k) * HID + tid] + cv * Ws[(8 + 2 * k) * HID + tid];
        }
        out[(size_t)n * HID + tid] = acc;
    }
}

// ---------------- per-graph node counts ----------------
__global__ void hist_batch(const int* __restrict__ batch) {
    __shared__ int h[GG];
    for (int i = threadIdx.x; i < GG; i += blockDim.x) h[i] = 0;
    __syncthreads();
    for (int i = blockIdx.x * blockDim.x + threadIdx.x; i < NN; i += gridDim.x * blockDim.x)
        atomicAdd(&h[batch[i]], 1);
    __syncthreads();
    for (int i = threadIdx.x; i < GG; i += blockDim.x)
        if (h[i]) atomicAdd(&g_cnt[i], h[i]);
}

// ---------------- CSR build: histogram -> single-block scan -> scatter ----------------
__global__ void hist_rows(const int* __restrict__ er) {
    int i = blockIdx.x * blockDim.x + threadIdx.x;
    if (i < EE) atomicAdd(&g_cursor[er[i]], 1);
}

__global__ void scan_all() { // 1 block, 1024 threads
    __shared__ int s[SCANT];
    int t = threadIdx.x;
    int base = t * CHUNK;
    int lim = min(base + CHUNK, NN);
    int sum = 0;
    for (int i = base; i < lim; i++) sum += g_cursor[i];
    s[t] = sum;
    __syncthreads();
    for (int off = 1; off < SCANT; off <<= 1) {
        int add = (t >= off) ? s[t - off] : 0;
        __syncthreads();
        s[t] += add;
        __syncthreads();
    }
    int run = s[t] - sum; // exclusive prefix
    if (t == 0) g_rowptr[NN] = EE;
    for (int i = base; i < lim; i++) {
        int c = g_cursor[i];
        g_rowptr[i] = run;
        g_cursor[i] = run;
        run += c;
    }
}

__global__ void scatter_edges(const int* __restrict__ er,
                              const int* __restrict__ ec,
                              const float* __restrict__ ev) {
    int i = blockIdx.x * blockDim.x + threadIdx.x;
    if (i < EE) {
        int p = atomicAdd(&g_cursor[er[i]], 1);
        g_cols[p] = ec[i];
        g_vals[p] = ev[i];
    }
}

// ---------------- SpMM (CSR, warp per row, float4 per lane, 4-edge unroll for MLP) ----------------
__global__ void spmm_csr(const float* __restrict__ H, float* __restrict__ out) {
    int w = (blockIdx.x * blockDim.x + threadIdx.x) >> 5;
    int lane = threadIdx.x & 31;
    if (w >= NN) return;
    int beg = g_rowptr[w];
    int end = g_rowptr[w + 1];
    int c4 = lane * 4;
    float4 acc = make_float4(0.f, 0.f, 0.f, 0.f);
    int e = beg;
    for (; e + 4 <= end; e += 4) {
        int   cA = __ldg(&g_cols[e]);
        int   cB = __ldg(&g_cols[e + 1]);
        int   cC = __ldg(&g_cols[e + 2]);
        int   cD = __ldg(&g_cols[e + 3]);
        float vA = __ldg(&g_vals[e]);
        float vB = __ldg(&g_vals[e + 1]);
        float vC = __ldg(&g_vals[e + 2]);
        float vD = __ldg(&g_vals[e + 3]);
        float4 hA = *(const float4*)&H[(size_t)cA * HID + c4];
        float4 hB = *(const float4*)&H[(size_t)cB * HID + c4];
        float4 hC = *(const float4*)&H[(size_t)cC * HID + c4];
        float4 hD = *(const float4*)&H[(size_t)cD * HID + c4];
        acc.x = fmaf(vA, hA.x, acc.x); acc.y = fmaf(vA, hA.y, acc.y);
        acc.z = fmaf(vA, hA.z, acc.z); acc.w = fmaf(vA, hA.w, acc.w);
        acc.x = fmaf(vB, hB.x, acc.x); acc.y = fmaf(vB, hB.y, acc.y);
        acc.z = fmaf(vB, hB.z, acc.z); acc.w = fmaf(vB, hB.w, acc.w);
        acc.x = fmaf(vC, hC.x, acc.x); acc.y = fmaf(vC, hC.y, acc.y);
        acc.z = fmaf(vC, hC.z, acc.z); acc.w = fmaf(vC, hC.w, acc.w);
        acc.x = fmaf(vD, hD.x, acc.x); acc.y = fmaf(vD, hD.y, acc.y);
        acc.z = fmaf(vD, hD.z, acc.z); acc.w = fmaf(vD, hD.w, acc.w);
    }
    for (; e < end; e++) {
        int c = __ldg(&g_cols[e]);
        float v = __ldg(&g_vals[e]);
        float4 hv = *(const float4*)&H[(size_t)c * HID + c4];
        acc.x = fmaf(v, hv.x, acc.x); acc.y = fmaf(v, hv.y, acc.y);
        acc.z = fmaf(v, hv.z, acc.z); acc.w = fmaf(v, hv.w, acc.w);
    }
    *(float4*)&out[(size_t)w * HID + c4] = acc;
}

// ---------------- GEMM (y = A @ W + b) fused with per-graph sum / sumsq stats ----------------
__global__ __launch_bounds__(256, 2)
void gemm_stats(const float* __restrict__ A, const float* __restrict__ W,
                const float* __restrict__ bias, const int* __restrict__ batch,
                float* __restrict__ Y) {
    extern __shared__ float sm[];
    float* Asm = sm;                 // [BM][APITCH]
    float* Wsm = sm + BM * APITCH;   // [HID][HID]
    int tid = threadIdx.x;
    int row0 = blockIdx.x * BM;

    const float4* Wg = (const float4*)W;
    float4* Wd = (float4*)Wsm;
    #pragma unroll
    for (int i = 0; i < 16; i++) Wd[tid + i * 256] = Wg[tid + i * 256];
    for (int i = tid; i < BM * 32; i += 256) {
        int r = i >> 5, k4 = (i & 31) << 2;
        *(float4*)&Asm[r * APITCH + k4] = *(const float4*)&A[(size_t)(row0 + r) * HID + k4];
    }
    __syncthreads();

    int tx = tid & 15, ty = tid >> 4;
    int cb = tx * 8, rb = ty * 4;
    float acc[4][8];
    #pragma unroll
    for (int r = 0; r < 4; r++)
        #pragma unroll
        for (int j = 0; j < 8; j++) acc[r][j] = 0.f;

    #pragma unroll 4
    for (int k = 0; k < HID; k++) {
        float a[4];
        #pragma unroll
        for (int r = 0; r < 4; r++) a[r] = Asm[(rb + r) * APITCH + k];
        float4 w0 = *(float4*)&Wsm[k * HID + cb];
        float4 w1 = *(float4*)&Wsm[k * HID + cb + 4];
        float wv[8] = {w0.x, w0.y, w0.z, w0.w, w1.x, w1.y, w1.z, w1.w};
        #pragma unroll
        for (int r = 0; r < 4; r++)
            #pragma unroll
            for (int j = 0; j < 8; j++)
                acc[r][j] = fmaf(a[r], wv[j], acc[r][j]);
    }

    float bv[8];
    #pragma unroll
    for (int j = 0; j < 8; j++) bv[j] = bias[cb + j];

    float s[8], q[8];
    #pragma unroll
    for (int j = 0; j < 8; j++) { s[j] = 0.f; q[j] = 0.f; }

    #pragma unroll
    for (int r = 0; r < 4; r++) {
        float y[8];
        #pragma unroll
        for (int j = 0; j < 8; j++) {
            y[j] = acc[r][j] + bv[j];
            s[j] += y[j];
            q[j] += y[j] * y[j];
        }
        size_t off = (size_t)(row0 + rb + r) * HID + cb;
        *(float4*)&Y[off]     = make_float4(y[0], y[1], y[2], y[3]);
        *(float4*)&Y[off + 4] = make_float4(y[4], y[5], y[6], y[7]);
    }

    int gfirst = batch[row0];
    int glast  = batch[row0 + BM - 1];
    if (gfirst == glast) {
        float* red = Asm; // reuse
        __syncthreads();
        *(float4*)&red[ty * APITCH + cb]     = make_float4(s[0], s[1], s[2], s[3]);
        *(float4*)&red[ty * APITCH + cb + 4] = make_float4(s[4], s[5], s[6], s[7]);
        __syncthreads();
        #pragma unroll
        for (int st = 8; st >= 1; st >>= 1) {
            if (ty < st) {
                #pragma unroll
                for (int j = 0; j < 8; j++)
                    red[ty * APITCH + cb + j] += red[(ty + st) * APITCH + cb + j];
            }
            __syncthreads();
        }
        if (ty == 0) {
            #pragma unroll
            for (int j = 0; j < 8; j++)
                atomicAdd(&g_sum[gfirst * HID + cb + j], red[cb + j]);
        }
        __syncthreads();
        *(float4*)&red[ty * APITCH + cb]     = make_float4(q[0], q[1], q[2], q[3]);
        *(float4*)&red[ty * APITCH + cb + 4] = make_float4(q[4], q[5], q[6], q[7]);
        __syncthreads();
        #pragma unroll
        for (int st = 8; st >= 1; st >>= 1) {
            if (ty < st) {
                #pragma unroll
                for (int j = 0; j < 8; j++)
                    red[ty * APITCH + cb + j] += red[(ty + st) * APITCH + cb + j];
            }
            __syncthreads();
        }
        if (ty == 0) {
            #pragma unroll
            for (int j = 0; j < 8; j++)
                atomicAdd(&g_sumsq[gfirst * HID + cb + j], red[cb + j]);
        }
    } else {
        #pragma unroll
        for (int r = 0; r < 4; r++) {
            int g = batch[row0 + rb + r];
            #pragma unroll
            for (int j = 0; j < 8; j++) {
                float y = acc[r][j] + bv[j];
                atomicAdd(&g_sum[g * HID + cb + j], y);
                atomicAdd(&g_sumsq[g * HID + cb + j], y * y);
            }
        }
    }
}

// ---------------- GraphNorm stat finalize (self-zeroes stats for next layer) ----------------
__global__ void finalize_stats(const float* __restrict__ alphas,
                               const float* __restrict__ gammas,
                               const float* __restrict__ betas, int l) {
    int i = blockIdx.x * blockDim.x + threadIdx.x;
    if (i >= GG * HID) return;
    int g = i >> 7, c = i & 127;
    float cnt = fmaxf((float)g_cnt[g], 1.f);
    float m  = g_sum[i] / cnt;
    float e2 = g_sumsq[i] / cnt;
    g_sum[i] = 0.f;    // ready for next layer's accumulation
    g_sumsq[i] = 0.f;
    float al = alphas[l];
    float var = e2 - al * (2.f - al) * m * m;
    float rstd = rsqrtf(fmaxf(var, 0.f) + EPSV);
    float ga = gammas[l * HID + c];
    g_scale[i] = rstd * ga;
    g_shift[i] = betas[l * HID + c] - al * m * rstd * ga;
}

// ---------------- normalize (+ optional relu) ----------------
__global__ void norm_kernel(const float* __restrict__ Y, const int* __restrict__ batch,
                            float* __restrict__ out, int relu) {
    int idx = blockIdx.x * blockDim.x + threadIdx.x;
    if (idx >= NN * 32) return;
    int n = idx >> 5, c4 = (idx & 31) * 4;
    int g = batch[n];
    float4 y  = *(const float4*)&Y[(size_t)n * HID + c4];
    float4 sc = *(const float4*)&g_scale[g * HID + c4];
    float4 sh = *(const float4*)&g_shift[g * HID + c4];
    float4 r;
    r.x = fmaf(y.x, sc.x, sh.x);
    r.y = fmaf(y.y, sc.y, sh.y);
    r.z = fmaf(y.z, sc.z, sh.z);
    r.w = fmaf(y.w, sc.w, sh.w);
    if (relu) {
        r.x = fmaxf(r.x, 0.f); r.y = fmaxf(r.y, 0.f);
        r.z = fmaxf(r.z, 0.f); r.w = fmaxf(r.w, 0.f);
    }
    *(float4*)&out[(size_t)n * HID + c4] = r;
}

// ---------------- launch ----------------
extern "C" void kernel_launch(void* const* d_in, const int* in_sizes, int n_in,
                              void* d_out, int out_size) {
    const float* x      = (const float*)d_in[0];
    const int*   er     = (const int*)d_in[1];
    const int*   ec     = (const int*)d_in[2];
    const float* ev     = (const float*)d_in[3];
    const int*   batch  = (const int*)d_in[4];
    const float* Win    = (const float*)d_in[5];
    const float* bin    = (const float*)d_in[6];
    const float* Ws     = (const float*)d_in[7];
    const float* bs     = (const float*)d_in[8];
    const float* alphas = (const float*)d_in[9];
    const float* gammas = (const float*)d_in[10];
    const float* betas  = (const float*)d_in[11];
    float* out = (float*)d_out;

    cudaFuncSetAttribute(gemm_stats, cudaFuncAttributeMaxDynamicSharedMemorySize, GEMM_SMEM);

    float *A, *B;
    cudaGetSymbolAddress((void**)&A, g_bufA);
    cudaGetSymbolAddress((void**)&B, g_bufB);

    // launch order chosen so ncu's -s 5 capture lands on the first spmm_csr
    embed_kernel<<<2048, 128>>>(x, Win, bin, A);      // #0 (also zeroes scratch)
    hist_batch<<<256, 256>>>(batch);                  // #1
    hist_rows<<<EE / 256, 256>>>(er);                 // #2
    scan_all<<<1, SCANT>>>();                         // #3
    scatter_edges<<<EE / 256, 256>>>(er, ec, ev);     // #4

    // Buffer flow per layer (round-1 proven scheme):
    //   in -> spmm -> agg -> gemm -> y(=in buffer, safe: spmm consumed it)
    //   -> norm -> agg (agg free after gemm)   => next layer's input is agg.
    for (int l = 0; l < NLAYER; l++) {
        const float* in = (l & 1) ? B : A;
        float* agg = (l & 1) ? A : B;
        float* y = (float*)in;                        // overwrite input buffer with y

        spmm_csr<<<(NN * 32 + 255) / 256, 256>>>(in, agg);   // #5 on l==0
        gemm_stats<<<NN / BM, 256, GEMM_SMEM>>>(agg, Ws + (size_t)l * HID * HID,
                                                bs + l * HID, batch, y);
        finalize_stats<<<(GG * HID) / 256, 256>>>(alphas, gammas, betas, l);
        float* nout = (l == NLAYER - 1) ? out : agg;  // norm writes agg (next layer's input)
        norm_kernel<<<(NN * 32) / 256, 256>>>(y, batch, nout, (l < NLAYER - 1) ? 1 : 0);
    }
}

// round 12
// speedup vs baseline: 1.2209x; 1.0197x over previous
#include <cuda_runtime.h>
#include <cuda_bf16.h>
#include <math.h>

#define NN     200000
#define EE     3200000
#define GG     256
#define HID    128
#define NLAYER 3
#define EPSV   1e-5f

#define SCANT  1024
#define CHUNK  196              // ceil(NN/SCANT)
#define BM     64               // gemm rows per block
#define APITCH 132              // padded A-tile pitch (floats)
#define GEMM_SMEM ((BM*APITCH + HID*HID) * 4)

// ---------------- scratch (device globals; no allocation allowed) ----------------
__device__ float g_bufA[(size_t)NN * HID];
__device__ float g_bufB[(size_t)NN * HID];
__device__ int   g_rowptr[NN + 1];
__device__ int   g_cursor[NN];
__device__ int   g_cols[EE];
__device__ float g_vals[EE];
__device__ int   g_chunk[SCANT];
__device__ float g_sum[GG * HID];
__device__ float g_sumsq[GG * HID];
__device__ float g_scale[GG * HID];
__device__ float g_shift[GG * HID];
__device__ int   g_cnt[GG];

// ---------------- node embedding + input projection (also zeroes all scratch) ----------------
__global__ void embed_kernel(const float* __restrict__ x,
                             const float* __restrict__ Win,
                             const float* __restrict__ bin,
                             float* __restrict__ out) {
    __shared__ float Ws[15 * HID];
    __shared__ float bs[HID];
    int tid = threadIdx.x; // blockDim = 128
    int gtid = blockIdx.x * 128 + tid; // 262144 threads total
    if (gtid < NN) g_cursor[gtid] = 0;
    if (gtid < GG) g_cnt[gtid] = 0;
    if (gtid < GG * HID) { g_sum[gtid] = 0.f; g_sumsq[gtid] = 0.f; }

    for (int i = tid; i < 15 * HID; i += 128) Ws[i] = Win[i];
    bs[tid] = bin[tid];
    __syncthreads();
    const float dts[4] = {1.0f, 0.1f, 0.01f, 0.001f};
    for (int n = blockIdx.x; n < NN; n += gridDim.x) {
        float t  = x[n * 3 + 0];
        float ar = x[n * 3 + 1];
        float ap = x[n * 3 + 2];
        int ti = min(max(__float2int_rz(t), 0), 5);
        float la = log1pf(ar);
        float acc = bs[tid] + Ws[ti * HID + tid] + la * Ws[6 * HID + tid];
        #pragma unroll
        for (int k = 0; k < 4; k++) {
            float sv, cv;
            sincosf(ap * dts[k], &sv, &cv);
            acc += sv * Ws[(7 + 2 * k) * HID + tid] + cv * Ws[(8 + 2 * k) * HID + tid];
        }
        out[(size_t)n * HID + tid] = acc;
    }
}

// ---------------- per-graph node counts ----------------
__global__ void hist_batch(const int* __restrict__ batch) {
    __shared__ int h[GG];
    for (int i = threadIdx.x; i < GG; i += blockDim.x) h[i] = 0;
    __syncthreads();
    for (int i = blockIdx.x * blockDim.x + threadIdx.x; i < NN; i += gridDim.x * blockDim.x)
        atomicAdd(&h[batch[i]], 1);
    __syncthreads();
    for (int i = threadIdx.x; i < GG; i += blockDim.x)
        if (h[i]) atomicAdd(&g_cnt[i], h[i]);
}

// ---------------- CSR build: histogram -> 3-kernel scan -> scatter ----------------
__global__ void hist_rows(const int* __restrict__ er) {
    int i = blockIdx.x * blockDim.x + threadIdx.x;
    if (i < EE) atomicAdd(&g_cursor[er[i]], 1);
}

__global__ void scan_chunks() { // grid 4 x 256
    int t = blockIdx.x * blockDim.x + threadIdx.x;
    if (t >= SCANT) return;
    int base = t * CHUNK;
    int lim = min(base + CHUNK, NN);
    int s = 0;
    for (int i = base; i < lim; i++) s += g_cursor[i];
    g_chunk[t] = s;
}

__global__ void scan_excl() { // 1 block, 1024 threads
    __shared__ int s[SCANT];
    int t = threadIdx.x;
    int v = g_chunk[t];
    s[t] = v;
    __syncthreads();
    for (int off = 1; off < SCANT; off <<= 1) {
        int add = (t >= off) ? s[t - off] : 0;
        __syncthreads();
        s[t] += add;
        __syncthreads();
    }
    g_chunk[t] = s[t] - v; // exclusive
}

__global__ void scan_write() { // grid 4 x 256
    int t = blockIdx.x * blockDim.x + threadIdx.x;
    if (t >= SCANT) return;
    if (t == 0) g_rowptr[NN] = EE;
    int base = t * CHUNK;
    int lim = min(base + CHUNK, NN);
    int run = g_chunk[t];
    for (int i = base; i < lim; i++) {
        int c = g_cursor[i];
        g_rowptr[i] = run;
        g_cursor[i] = run;
        run += c;
    }
}

__global__ void scatter_edges(const int* __restrict__ er,
                              const int* __restrict__ ec,
                              const float* __restrict__ ev) {
    int i = blockIdx.x * blockDim.x + threadIdx.x;
    if (i < EE) {
        int p = atomicAdd(&g_cursor[er[i]], 1);
        g_cols[p] = ec[i];
        g_vals[p] = ev[i];
    }
}

// ---------------- SpMM (CSR, warp per row, float4 per lane, 4-edge unroll) ----------------
__global__ void spmm_csr(const float* __restrict__ H, float* __restrict__ out) {
    int w = (blockIdx.x * blockDim.x + threadIdx.x) >> 5;
    int lane = threadIdx.x & 31;
    if (w >= NN) return;
    int beg = g_rowptr[w];
    int end = g_rowptr[w + 1];
    int c4 = lane * 4;
    float4 acc = make_float4(0.f, 0.f, 0.f, 0.f);
    int e = beg;
    for (; e + 4 <= end; e += 4) {
        int   cA = __ldg(&g_cols[e]);
        int   cB = __ldg(&g_cols[e + 1]);
        int   cC = __ldg(&g_cols[e + 2]);
        int   cD = __ldg(&g_cols[e + 3]);
        float vA = __ldg(&g_vals[e]);
        float vB = __ldg(&g_vals[e + 1]);
        float vC = __ldg(&g_vals[e + 2]);
        float vD = __ldg(&g_vals[e + 3]);
        float4 hA = *(const float4*)&H[(size_t)cA * HID + c4];
        float4 hB = *(const float4*)&H[(size_t)cB * HID + c4];
        float4 hC = *(const float4*)&H[(size_t)cC * HID + c4];
        float4 hD = *(const float4*)&H[(size_t)cD * HID + c4];
        acc.x = fmaf(vA, hA.x, acc.x); acc.y = fmaf(vA, hA.y, acc.y);
        acc.z = fmaf(vA, hA.z, acc.z); acc.w = fmaf(vA, hA.w, acc.w);
        acc.x = fmaf(vB, hB.x, acc.x); acc.y = fmaf(vB, hB.y, acc.y);
        acc.z = fmaf(vB, hB.z, acc.z); acc.w = fmaf(vB, hB.w, acc.w);
        acc.x = fmaf(vC, hC.x, acc.x); acc.y = fmaf(vC, hC.y, acc.y);
        acc.z = fmaf(vC, hC.z, acc.z); acc.w = fmaf(vC, hC.w, acc.w);
        acc.x = fmaf(vD, hD.x, acc.x); acc.y = fmaf(vD, hD.y, acc.y);
        acc.z = fmaf(vD, hD.z, acc.z); acc.w = fmaf(vD, hD.w, acc.w);
    }
    for (; e < end; e++) {
        int c = __ldg(&g_cols[e]);
        float v = __ldg(&g_vals[e]);
        float4 hv = *(const float4*)&H[(size_t)c * HID + c4];
        acc.x = fmaf(v, hv.x, acc.x); acc.y = fmaf(v, hv.y, acc.y);
        acc.z = fmaf(v, hv.z, acc.z); acc.w = fmaf(v, hv.w, acc.w);
    }
    *(float4*)&out[(size_t)w * HID + c4] = acc;
}

// ---------------- fp32 SIMT GEMM (y = A @ W + b) + fused per-graph stats ----------------
__global__ __launch_bounds__(256, 2)
void gemm_stats(const float* __restrict__ A, const float* __restrict__ W,
                const float* __restrict__ bias, const int* __restrict__ batch,
                float* __restrict__ Y) {
    extern __shared__ float sm[];
    float* Asm = sm;                 // [BM][APITCH]
    float* Wsm = sm + BM * APITCH;   // [HID][HID]
    int tid = threadIdx.x;
    int row0 = blockIdx.x * BM;

    const float4* Wg = (const float4*)W;
    float4* Wd = (float4*)Wsm;
    #pragma unroll
    for (int i = 0; i < 16; i++) Wd[tid + i * 256] = Wg[tid + i * 256];
    for (int i = tid; i < BM * 32; i += 256) {
        int r = i >> 5, k4 = (i & 31) << 2;
        *(float4*)&Asm[r * APITCH + k4] = *(const float4*)&A[(size_t)(row0 + r) * HID + k4];
    }
    __syncthreads();

    int tx = tid & 15, ty = tid >> 4;
    int cb = tx * 8, rb = ty * 4;
    float acc[4][8];
    #pragma unroll
    for (int r = 0; r < 4; r++)
        #pragma unroll
        for (int j = 0; j < 8; j++) acc[r][j] = 0.f;

    #pragma unroll 4
    for (int k = 0; k < HID; k++) {
        float a[4];
        #pragma unroll
        for (int r = 0; r < 4; r++) a[r] = Asm[(rb + r) * APITCH + k];
        float4 w0 = *(float4*)&Wsm[k * HID + cb];
        float4 w1 = *(float4*)&Wsm[k * HID + cb + 4];
        float wv[8] = {w0.x, w0.y, w0.z, w0.w, w1.x, w1.y, w1.z, w1.w};
        #pragma unroll
        for (int r = 0; r < 4; r++)
            #pragma unroll
            for (int j = 0; j < 8; j++)
                acc[r][j] = fmaf(a[r], wv[j], acc[r][j]);
    }

    float bv[8];
    #pragma unroll
    for (int j = 0; j < 8; j++) bv[j] = bias[cb + j];

    float s[8], q[8];
    #pragma unroll
    for (int j = 0; j < 8; j++) { s[j] = 0.f; q[j] = 0.f; }

    #pragma unroll
    for (int r = 0; r < 4; r++) {
        float y[8];
        #pragma unroll
        for (int j = 0; j < 8; j++) {
            y[j] = acc[r][j] + bv[j];
            s[j] += y[j];
            q[j] += y[j] * y[j];
        }
        size_t off = (size_t)(row0 + rb + r) * HID + cb;
        *(float4*)&Y[off]     = make_float4(y[0], y[1], y[2], y[3]);
        *(float4*)&Y[off + 4] = make_float4(y[4], y[5], y[6], y[7]);
    }

    int gfirst = batch[row0];
    int glast  = batch[row0 + BM - 1];
    if (gfirst == glast) {
        float* red = Asm; // reuse
        __syncthreads();
        *(float4*)&red[ty * APITCH + cb]     = make_float4(s[0], s[1], s[2], s[3]);
        *(float4*)&red[ty * APITCH + cb + 4] = make_float4(s[4], s[5], s[6], s[7]);
        __syncthreads();
        #pragma unroll
        for (int st = 8; st >= 1; st >>= 1) {
            if (ty < st) {
                #pragma unroll
                for (int j = 0; j < 8; j++)
                    red[ty * APITCH + cb + j] += red[(ty + st) * APITCH + cb + j];
            }
            __syncthreads();
        }
        if (ty == 0) {
            #pragma unroll
            for (int j = 0; j < 8; j++)
                atomicAdd(&g_sum[gfirst * HID + cb + j], red[cb + j]);
        }
        __syncthreads();
        *(float4*)&red[ty * APITCH + cb]     = make_float4(q[0], q[1], q[2], q[3]);
        *(float4*)&red[ty * APITCH + cb + 4] = make_float4(q[4], q[5], q[6], q[7]);
        __syncthreads();
        #pragma unroll
        for (int st = 8; st >= 1; st >>= 1) {
            if (ty < st) {
                #pragma unroll
                for (int j = 0; j < 8; j++)
                    red[ty * APITCH + cb + j] += red[(ty + st) * APITCH + cb + j];
            }
            __syncthreads();
        }
        if (ty == 0) {
            #pragma unroll
            for (int j = 0; j < 8; j++)
                atomicAdd(&g_sumsq[gfirst * HID + cb + j], red[cb + j]);
        }
    } else {
        #pragma unroll
        for (int r = 0; r < 4; r++) {
            int g = batch[row0 + rb + r];
            #pragma unroll
            for (int j = 0; j < 8; j++) {
                float y = acc[r][j] + bv[j];
                atomicAdd(&g_sum[g * HID + cb + j], y);
                atomicAdd(&g_sumsq[g * HID + cb + j], y * y);
            }
        }
    }
}

// ---------------- GraphNorm stat finalize (self-zeroes stats for next layer) ----------------
__global__ void finalize_stats(const float* __restrict__ alphas,
                               const float* __restrict__ gammas,
                               const float* __restrict__ betas, int l) {
    int i = blockIdx.x * blockDim.x + threadIdx.x;
    if (i >= GG * HID) return;
    int g = i >> 7, c = i & 127;
    float cnt = fmaxf((float)g_cnt[g], 1.f);
    float m  = g_sum[i] / cnt;
    float e2 = g_sumsq[i] / cnt;
    g_sum[i] = 0.f;
    g_sumsq[i] = 0.f;
    float al = alphas[l];
    float var = e2 - al * (2.f - al) * m * m;
    float rstd = rsqrtf(fmaxf(var, 0.f) + EPSV);
    float ga = gammas[l * HID + c];
    g_scale[i] = rstd * ga;
    g_shift[i] = betas[l * HID + c] - al * m * rstd * ga;
}

// ---------------- normalize (+ optional relu) ----------------
__global__ void norm_kernel(const float* __restrict__ Y, const int* __restrict__ batch,
                            float* __restrict__ out, int relu) {
    int idx = blockIdx.x * blockDim.x + threadIdx.x;
    if (idx >= NN * 32) return;
    int n = idx >> 5, c4 = (idx & 31) * 4;
    int g = batch[n];
    float4 y  = *(const float4*)&Y[(size_t)n * HID + c4];
    float4 sc = *(const float4*)&g_scale[g * HID + c4];
    float4 sh = *(const float4*)&g_shift[g * HID + c4];
    float4 r;
    r.x = fmaf(y.x, sc.x, sh.x);
    r.y = fmaf(y.y, sc.y, sh.y);
    r.z = fmaf(y.z, sc.z, sh.z);
    r.w = fmaf(y.w, sc.w, sh.w);
    if (relu) {
        r.x = fmaxf(r.x, 0.f); r.y = fmaxf(r.y, 0.f);
        r.z = fmaxf(r.z, 0.f); r.w = fmaxf(r.w, 0.f);
    }
    *(float4*)&out[(size_t)n * HID + c4] = r;
}

// ---------------- launch ----------------
extern "C" void kernel_launch(void* const* d_in, const int* in_sizes, int n_in,
                              void* d_out, int out_size) {
    const float* x      = (const float*)d_in[0];
    const int*   er     = (const int*)d_in[1];
    const int*   ec     = (const int*)d_in[2];
    const float* ev     = (const float*)d_in[3];
    const int*   batch  = (const int*)d_in[4];
    const float* Win    = (const float*)d_in[5];
    const float* bin    = (const float*)d_in[6];
    const float* Ws     = (const float*)d_in[7];
    const float* bs     = (const float*)d_in[8];
    const float* alphas = (const float*)d_in[9];
    const float* gammas = (const float*)d_in[10];
    const float* betas  = (const float*)d_in[11];
    float* out = (float*)d_out;

    cudaFuncSetAttribute(gemm_stats, cudaFuncAttributeMaxDynamicSharedMemorySize, GEMM_SMEM);

    float *A, *B;
    cudaGetSymbolAddress((void**)&A, g_bufA);
    cudaGetSymbolAddress((void**)&B, g_bufB);

    embed_kernel<<<2048, 128>>>(x, Win, bin, A);      // also zeroes scratch
    hist_batch<<<256, 256>>>(batch);
    hist_rows<<<EE / 256, 256>>>(er);
    scan_chunks<<<4, 256>>>();
    scan_excl<<<1, SCANT>>>();
    scan_write<<<4, 256>>>();
    scatter_edges<<<EE / 256, 256>>>(er, ec, ev);

    // Buffer flow per layer:
    //   in -> spmm -> agg -> gemm -> y(=in buffer) -> norm -> agg (next input)
    for (int l = 0; l < NLAYER; l++) {
        const float* in = (l & 1) ? B : A;
        float* agg = (l & 1) ? A : B;
        float* y = (float*)in;

        spmm_csr<<<(NN * 32 + 255) / 256, 256>>>(in, agg);
        gemm_stats<<<NN / BM, 256, GEMM_SMEM>>>(agg, Ws + (size_t)l * HID * HID,
                                                bs + l * HID, batch, y);
        finalize_stats<<<(GG * HID) / 256, 256>>>(alphas, gammas, betas, l);
        float* nout = (l == NLAYER - 1) ? out : agg;
        norm_kernel<<<(NN * 32) / 256, 256>>>(y, batch, nout, (l < NLAYER - 1) ? 1 : 0);
    }
}

// round 14
// speedup vs baseline: 1.2255x; 1.0038x over previous
#include <cuda_runtime.h>
#include <cuda_bf16.h>
#include <math.h>

#define NN     200000
#define EE     3200000
#define GG     256
#define HID    128
#define NLAYER 3
#define EPSV   1e-5f

#define SCANT  1024
#define CHUNK  196              // ceil(NN/SCANT)
#define BM     64               // gemm rows per block
#define APITCH 132              // padded A-tile pitch (floats)
#define GEMM_SMEM ((BM*APITCH + HID*HID) * 4)

// ---------------- scratch (device globals; no allocation allowed) ----------------
__device__ float g_bufA[(size_t)NN * HID];
__device__ float g_bufB[(size_t)NN * HID];
__device__ int   g_rowptr[NN + 1];
__device__ int   g_cursor[NN];
__device__ int   g_cols[EE];
__device__ float g_vals[EE];
__device__ int   g_chunk[SCANT];
__device__ float g_sum[GG * HID];
__device__ float g_sumsq[GG * HID];
__device__ float g_scale[GG * HID];
__device__ float g_shift[GG * HID];
__device__ int   g_cnt[GG];

// ---------------- node embedding + input projection (also zeroes all scratch) ----------------
__global__ void embed_kernel(const float* __restrict__ x,
                             const float* __restrict__ Win,
                             const float* __restrict__ bin,
                             float* __restrict__ out) {
    __shared__ float Ws[15 * HID];
    __shared__ float bs[HID];
    int tid = threadIdx.x; // blockDim = 128
    int gtid = blockIdx.x * 128 + tid; // 262144 threads total
    if (gtid < NN) g_cursor[gtid] = 0;
    if (gtid < GG) g_cnt[gtid] = 0;
    if (gtid < GG * HID) { g_sum[gtid] = 0.f; g_sumsq[gtid] = 0.f; }

    for (int i = tid; i < 15 * HID; i += 128) Ws[i] = Win[i];
    bs[tid] = bin[tid];
    __syncthreads();
    const float dts[4] = {1.0f, 0.1f, 0.01f, 0.001f};
    for (int n = blockIdx.x; n < NN; n += gridDim.x) {
        float t  = x[n * 3 + 0];
        float ar = x[n * 3 + 1];
        float ap = x[n * 3 + 2];
        int ti = min(max(__float2int_rz(t), 0), 5);
        float la = log1pf(ar);
        float acc = bs[tid] + Ws[ti * HID + tid] + la * Ws[6 * HID + tid];
        #pragma unroll
        for (int k = 0; k < 4; k++) {
            float sv, cv;
            sincosf(ap * dts[k], &sv, &cv);
            acc += sv * Ws[(7 + 2 * k) * HID + tid] + cv * Ws[(8 + 2 * k) * HID + tid];
        }
        out[(size_t)n * HID + tid] = acc;
    }
}

// ---------------- per-graph node counts ----------------
__global__ void hist_batch(const int* __restrict__ batch) {
    __shared__ int h[GG];
    for (int i = threadIdx.x; i < GG; i += blockDim.x) h[i] = 0;
    __syncthreads();
    for (int i = blockIdx.x * blockDim.x + threadIdx.x; i < NN; i += gridDim.x * blockDim.x)
        atomicAdd(&h[batch[i]], 1);
    __syncthreads();
    for (int i = threadIdx.x; i < GG; i += blockDim.x)
        if (h[i]) atomicAdd(&g_cnt[i], h[i]);
}

// ---------------- CSR build: histogram -> 3-kernel scan -> scatter ----------------
__global__ void hist_rows(const int* __restrict__ er) {
    int i = blockIdx.x * blockDim.x + threadIdx.x;
    if (i < EE) atomicAdd(&g_cursor[er[i]], 1);
}

__global__ void scan_chunks() { // grid 4 x 256
    int t = blockIdx.x * blockDim.x + threadIdx.x;
    if (t >= SCANT) return;
    int base = t * CHUNK;
    int lim = min(base + CHUNK, NN);
    int s = 0;
    for (int i = base; i < lim; i++) s += g_cursor[i];
    g_chunk[t] = s;
}

__global__ void scan_excl() { // 1 block, 1024 threads
    __shared__ int s[SCANT];
    int t = threadIdx.x;
    int v = g_chunk[t];
    s[t] = v;
    __syncthreads();
    for (int off = 1; off < SCANT; off <<= 1) {
        int add = (t >= off) ? s[t - off] : 0;
        __syncthreads();
        s[t] += add;
        __syncthreads();
    }
    g_chunk[t] = s[t] - v; // exclusive
}

__global__ void scan_write() { // grid 4 x 256
    int t = blockIdx.x * blockDim.x + threadIdx.x;
    if (t >= SCANT) return;
    if (t == 0) g_rowptr[NN] = EE;
    int base = t * CHUNK;
    int lim = min(base + CHUNK, NN);
    int run = g_chunk[t];
    for (int i = base; i < lim; i++) {
        int c = g_cursor[i];
        g_rowptr[i] = run;
        g_cursor[i] = run;
        run += c;
    }
}

__global__ void scatter_edges(const int* __restrict__ er,
                              const int* __restrict__ ec,
                              const float* __restrict__ ev) {
    int i = blockIdx.x * blockDim.x + threadIdx.x;
    if (i < EE) {
        int p = atomicAdd(&g_cursor[er[i]], 1);
        g_cols[p] = ec[i];
        g_vals[p] = ev[i];
    }
}

// ---------------- SpMM (CSR, warp per row, float4 per lane, 8-edge unroll) ----------------
// H gathers use default (caching) loads -> stay hot in L2.
// Output is written with .cs (evict-first) so the agg stream doesn't thrash L2.
__global__ void spmm_csr(const float* __restrict__ H, float* __restrict__ out) {
    int w = (blockIdx.x * blockDim.x + threadIdx.x) >> 5;
    int lane = threadIdx.x & 31;
    if (w >= NN) return;
    int beg = g_rowptr[w];
    int end = g_rowptr[w + 1];
    int c4 = lane * 4;
    float4 acc = make_float4(0.f, 0.f, 0.f, 0.f);
    int e = beg;
    for (; e + 8 <= end; e += 8) {
        int   c0 = __ldg(&g_cols[e]);
        int   c1 = __ldg(&g_cols[e + 1]);
        int   c2 = __ldg(&g_cols[e + 2]);
        int   c3 = __ldg(&g_cols[e + 3]);
        int   c5 = __ldg(&g_cols[e + 4]);
        int   c6 = __ldg(&g_cols[e + 5]);
        int   c7 = __ldg(&g_cols[e + 6]);
        int   c8 = __ldg(&g_cols[e + 7]);
        float v0 = __ldg(&g_vals[e]);
        float v1 = __ldg(&g_vals[e + 1]);
        float v2 = __ldg(&g_vals[e + 2]);
        float v3 = __ldg(&g_vals[e + 3]);
        float v5 = __ldg(&g_vals[e + 4]);
        float v6 = __ldg(&g_vals[e + 5]);
        float v7 = __ldg(&g_vals[e + 6]);
        float v8 = __ldg(&g_vals[e + 7]);
        float4 h0 = *(const float4*)&H[(size_t)c0 * HID + c4];
        float4 h1 = *(const float4*)&H[(size_t)c1 * HID + c4];
        float4 h2 = *(const float4*)&H[(size_t)c2 * HID + c4];
        float4 h3 = *(const float4*)&H[(size_t)c3 * HID + c4];
        float4 h5 = *(const float4*)&H[(size_t)c5 * HID + c4];
        float4 h6 = *(const float4*)&H[(size_t)c6 * HID + c4];
        float4 h7 = *(const float4*)&H[(size_t)c7 * HID + c4];
        float4 h8 = *(const float4*)&H[(size_t)c8 * HID + c4];
        acc.x = fmaf(v0, h0.x, acc.x); acc.y = fmaf(v0, h0.y, acc.y);
        acc.z = fmaf(v0, h0.z, acc.z); acc.w = fmaf(v0, h0.w, acc.w);
        acc.x = fmaf(v1, h1.x, acc.x); acc.y = fmaf(v1, h1.y, acc.y);
        acc.z = fmaf(v1, h1.z, acc.z); acc.w = fmaf(v1, h1.w, acc.w);
        acc.x = fmaf(v2, h2.x, acc.x); acc.y = fmaf(v2, h2.y, acc.y);
        acc.z = fmaf(v2, h2.z, acc.z); acc.w = fmaf(v2, h2.w, acc.w);
        acc.x = fmaf(v3, h3.x, acc.x); acc.y = fmaf(v3, h3.y, acc.y);
        acc.z = fmaf(v3, h3.z, acc.z); acc.w = fmaf(v3, h3.w, acc.w);
        acc.x = fmaf(v5, h5.x, acc.x); acc.y = fmaf(v5, h5.y, acc.y);
        acc.z = fmaf(v5, h5.z, acc.z); acc.w = fmaf(v5, h5.w, acc.w);
        acc.x = fmaf(v6, h6.x, acc.x); acc.y = fmaf(v6, h6.y, acc.y);
        acc.z = fmaf(v6, h6.z, acc.z); acc.w = fmaf(v6, h6.w, acc.w);
        acc.x = fmaf(v7, h7.x, acc.x); acc.y = fmaf(v7, h7.y, acc.y);
        acc.z = fmaf(v7, h7.z, acc.z); acc.w = fmaf(v7, h7.w, acc.w);
        acc.x = fmaf(v8, h8.x, acc.x); acc.y = fmaf(v8, h8.y, acc.y);
        acc.z = fmaf(v8, h8.z, acc.z); acc.w = fmaf(v8, h8.w, acc.w);
    }
    for (; e < end; e++) {
        int c = __ldg(&g_cols[e]);
        float v = __ldg(&g_vals[e]);
        float4 hv = *(const float4*)&H[(size_t)c * HID + c4];
        acc.x = fmaf(v, hv.x, acc.x); acc.y = fmaf(v, hv.y, acc.y);
        acc.z = fmaf(v, hv.z, acc.z); acc.w = fmaf(v, hv.w, acc.w);
    }
    __stcs((float4*)&out[(size_t)w * HID + c4], acc);
}

// ---------------- fp32 SIMT GEMM (y = A @ W + b) + fused per-graph stats ----------------
// A is read once (.cs), y written once (.cs) -> keep L2 for the h array.
__global__ __launch_bounds__(256, 2)
void gemm_stats(const float* __restrict__ A, const float* __restrict__ W,
                const float* __restrict__ bias, const int* __restrict__ batch,
                float* __restrict__ Y) {
    extern __shared__ float sm[];
    float* Asm = sm;                 // [BM][APITCH]
    float* Wsm = sm + BM * APITCH;   // [HID][HID]
    int tid = threadIdx.x;
    int row0 = blockIdx.x * BM;

    const float4* Wg = (const float4*)W;
    float4* Wd = (float4*)Wsm;
    #pragma unroll
    for (int i = 0; i < 16; i++) Wd[tid + i * 256] = Wg[tid + i * 256];
    for (int i = tid; i < BM * 32; i += 256) {
        int r = i >> 5, k4 = (i & 31) << 2;
        float4 a = __ldcs((const float4*)&A[(size_t)(row0 + r) * HID + k4]);
        *(float4*)&Asm[r * APITCH + k4] = a;
    }
    __syncthreads();

    int tx = tid & 15, ty = tid >> 4;
    int cb = tx * 8, rb = ty * 4;
    float acc[4][8];
    #pragma unroll
    for (int r = 0; r < 4; r++)
        #pragma unroll
        for (int j = 0; j < 8; j++) acc[r][j] = 0.f;

    #pragma unroll 4
    for (int k = 0; k < HID; k++) {
        float a[4];
        #pragma unroll
        for (int r = 0; r < 4; r++) a[r] = Asm[(rb + r) * APITCH + k];
        float4 w0 = *(float4*)&Wsm[k * HID + cb];
        float4 w1 = *(float4*)&Wsm[k * HID + cb + 4];
        float wv[8] = {w0.x, w0.y, w0.z, w0.w, w1.x, w1.y, w1.z, w1.w};
        #pragma unroll
        for (int r = 0; r < 4; r++)
            #pragma unroll
            for (int j = 0; j < 8; j++)
                acc[r][j] = fmaf(a[r], wv[j], acc[r][j]);
    }

    float bv[8];
    #pragma unroll
    for (int j = 0; j < 8; j++) bv[j] = bias[cb + j];

    float s[8], q[8];
    #pragma unroll
    for (int j = 0; j < 8; j++) { s[j] = 0.f; q[j] = 0.f; }

    #pragma unroll
    for (int r = 0; r < 4; r++) {
        float y[8];
        #pragma unroll
        for (int j = 0; j < 8; j++) {
            y[j] = acc[r][j] + bv[j];
            s[j] += y[j];
            q[j] += y[j] * y[j];
        }
        size_t off = (size_t)(row0 + rb + r) * HID + cb;
        __stcs((float4*)&Y[off],     make_float4(y[0], y[1], y[2], y[3]));
        __stcs((float4*)&Y[off + 4], make_float4(y[4], y[5], y[6], y[7]));
    }

    int gfirst = batch[row0];
    int glast  = batch[row0 + BM - 1];
    if (gfirst == glast) {
        float* red = Asm; // reuse
        __syncthreads();
        *(float4*)&red[ty * APITCH + cb]     = make_float4(s[0], s[1], s[2], s[3]);
        *(float4*)&red[ty * APITCH + cb + 4] = make_float4(s[4], s[5], s[6], s[7]);
        __syncthreads();
        #pragma unroll
        for (int st = 8; st >= 1; st >>= 1) {
            if (ty < st) {
                #pragma unroll
                for (int j = 0; j < 8; j++)
                    red[ty * APITCH + cb + j] += red[(ty + st) * APITCH + cb + j];
            }
            __syncthreads();
        }
        if (ty == 0) {
            #pragma unroll
            for (int j = 0; j < 8; j++)
                atomicAdd(&g_sum[gfirst * HID + cb + j], red[cb + j]);
        }
        __syncthreads();
        *(float4*)&red[ty * APITCH + cb]     = make_float4(q[0], q[1], q[2], q[3]);
        *(float4*)&red[ty * APITCH + cb + 4] = make_float4(q[4], q[5], q[6], q[7]);
        __syncthreads();
        #pragma unroll
        for (int st = 8; st >= 1; st >>= 1) {
            if (ty < st) {
                #pragma unroll
                for (int j = 0; j < 8; j++)
                    red[ty * APITCH + cb + j] += red[(ty + st) * APITCH + cb + j];
            }
            __syncthreads();
        }
        if (ty == 0) {
            #pragma unroll
            for (int j = 0; j < 8; j++)
                atomicAdd(&g_sumsq[gfirst * HID + cb + j], red[cb + j]);
        }
    } else {
        #pragma unroll
        for (int r = 0; r < 4; r++) {
            int g = batch[row0 + rb + r];
            #pragma unroll
            for (int j = 0; j < 8; j++) {
                float y = acc[r][j] + bv[j];
                atomicAdd(&g_sum[g * HID + cb + j], y);
                atomicAdd(&g_sumsq[g * HID + cb + j], y * y);
            }
        }
    }
}

// ---------------- GraphNorm stat finalize (self-zeroes stats for next layer) ----------------
__global__ void finalize_stats(const float* __restrict__ alphas,
                               const float* __restrict__ gammas,
                               const float* __restrict__ betas, int l) {
    int i = blockIdx.x * blockDim.x + threadIdx.x;
    if (i >= GG * HID) return;
    int g = i >> 7, c = i & 127;
    float cnt = fmaxf((float)g_cnt[g], 1.f);
    float m  = g_sum[i] / cnt;
    float e2 = g_sumsq[i] / cnt;
    g_sum[i] = 0.f;
    g_sumsq[i] = 0.f;
    float al = alphas[l];
    float var = e2 - al * (2.f - al) * m * m;
    float rstd = rsqrtf(fmaxf(var, 0.f) + EPSV);
    float ga = gammas[l * HID + c];
    g_scale[i] = rstd * ga;
    g_shift[i] = betas[l * HID + c] - al * m * rstd * ga;
}

// ---------------- normalize (+ optional relu); streaming loads/stores ----------------
__global__ void norm_kernel(const float* __restrict__ Y, const int* __restrict__ batch,
                            float* __restrict__ out, int relu) {
    int idx = blockIdx.x * blockDim.x + threadIdx.x;
    if (idx >= NN * 32) return;
    int n = idx >> 5, c4 = (idx & 31) * 4;
    int g = batch[n];
    float4 y  = __ldcs((const float4*)&Y[(size_t)n * HID + c4]);
    float4 sc = *(const float4*)&g_scale[g * HID + c4];
    float4 sh = *(const float4*)&g_shift[g * HID + c4];
    float4 r;
    r.x = fmaf(y.x, sc.x, sh.x);
    r.y = fmaf(y.y, sc.y, sh.y);
    r.z = fmaf(y.z, sc.z, sh.z);
    r.w = fmaf(y.w, sc.w, sh.w);
    if (relu) {
        r.x = fmaxf(r.x, 0.f); r.y = fmaxf(r.y, 0.f);
        r.z = fmaxf(r.z, 0.f); r.w = fmaxf(r.w, 0.f);
    }
    // note: out becomes next layer's gather target -> default store (keep in L2)
    *(float4*)&out[(size_t)n * HID + c4] = r;
}

// ---------------- launch ----------------
extern "C" void kernel_launch(void* const* d_in, const int* in_sizes, int n_in,
                              void* d_out, int out_size) {
    const float* x      = (const float*)d_in[0];
    const int*   er     = (const int*)d_in[1];
    const int*   ec     = (const int*)d_in[2];
    const float* ev     = (const float*)d_in[3];
    const int*   batch  = (const int*)d_in[4];
    const float* Win    = (const float*)d_in[5];
    const float* bin    = (const float*)d_in[6];
    const float* Ws     = (const float*)d_in[7];
    const float* bs     = (const float*)d_in[8];
    const float* alphas = (const float*)d_in[9];
    const float* gammas = (const float*)d_in[10];
    const float* betas  = (const float*)d_in[11];
    float* out = (float*)d_out;

    cudaFuncSetAttribute(gemm_stats, cudaFuncAttributeMaxDynamicSharedMemorySize, GEMM_SMEM);

    float *A, *B;
    cudaGetSymbolAddress((void**)&A, g_bufA);
    cudaGetSymbolAddress((void**)&B, g_bufB);

    embed_kernel<<<2048, 128>>>(x, Win, bin, A);      // also zeroes scratch
    hist_batch<<<256, 256>>>(batch);
    hist_rows<<<EE / 256, 256>>>(er);
    scan_chunks<<<4, 256>>>();
    scan_excl<<<1, SCANT>>>();
    scan_write<<<4, 256>>>();
    scatter_edges<<<EE / 256, 256>>>(er, ec, ev);

    // Buffer flow per layer:
    //   in -> spmm -> agg -> gemm -> y(=in buffer) -> norm -> agg (next input)
    for (int l = 0; l < NLAYER; l++) {
        const float* in = (l & 1) ? B : A;
        float* agg = (l & 1) ? A : B;
        float* y = (float*)in;

        spmm_csr<<<(NN * 32 + 255) / 256, 256>>>(in, agg);
        gemm_stats<<<NN / BM, 256, GEMM_SMEM>>>(agg, Ws + (size_t)l * HID * HID,
                                                bs + l * HID, batch, y);
        finalize_stats<<<(GG * HID) / 256, 256>>>(alphas, gammas, betas, l);
        float* nout = (l == NLAYER - 1) ? out : agg;
        norm_kernel<<<(NN * 32) / 256, 256>>>(y, batch, nout, (l < NLAYER - 1) ? 1 : 0);
    }
}